// round 7
// baseline (speedup 1.0000x reference)
#include <cuda_runtime.h>
#include <math.h>

#define HH 112
#define WW 112
#define NPIX (HH*WW)          // 12544
#define GRID 7
#define NCELL 49
#define NFEAT 1822
#define TWO_PI_F 6.283185307179586f

// ---- smem layout (floats) ----
#define SG_OFF 0                      // gray, 112 rows x 132 (10-col zero halo)
#define T0_OFF 14784                  // h-pass tmp orient0, 132 rows x 112 (10-row zero halo)
#define T1_OFF 29568                  // h-pass tmp orient1
#define CA_OFF 44352                  // cell accumulators [49][16] (15 used)
#define GA_OFF 45136                  // gabor cell sums [49][2] (pad to 100)
#define HI_OFF 45236                  // int hist [49][24]
#define IS_OFF 46412                  // image-level sums [9] (+pad)
#define SMEM_FLOATS (IS_OFF + 16)
#define MEGA_SMEM (SMEM_FLOATS * sizeof(float))   // ~185.7 KB

__global__ void __launch_bounds__(1024) mega(const float* __restrict__ img,
                                             const float* __restrict__ gk0,
                                             const float* __restrict__ gk1,
                                             float* __restrict__ out)
{
    extern __shared__ float sm[];
    float* sg = sm + SG_OFF;
    float* t0 = sm + T0_OFF;
    float* t1 = sm + T1_OFF;
    float* ca = sm + CA_OFF;
    float* ga = sm + GA_OFF;
    int*   hi = (int*)(sm + HI_OFF);
    float* is = sm + IS_OFF;

    const int b    = blockIdx.x;
    const int tid  = threadIdx.x;
    const int lane = tid & 31;
    const int wid  = tid >> 5;
    const float* base = img + (size_t)b * 3 * NPIX;

    // ---- zero init (hist, accumulators, halo regions) ----
    for (int i = tid; i < 20 * 112; i += 1024) {       // t0/t1 halo rows 0..9, 122..131
        int rr = i / 112, cc = i % 112;
        int row = (rr < 10) ? rr : rr + 112;
        t0[row * 112 + cc] = 0.0f;
        t1[row * 112 + cc] = 0.0f;
    }
    for (int i = tid; i < 112 * 20; i += 1024) {       // sg halo cols 0..9, 122..131
        int rr = i / 20, cc = i % 20;
        int col = (cc < 10) ? cc : cc + 112;
        sg[rr * 132 + col] = 0.0f;
    }
    for (int i = tid; i < 784; i += 1024)  ca[i] = 0.0f;
    if (tid < 100) ga[tid] = 0.0f;
    for (int i = tid; i < 1176; i += 1024) hi[i] = 0;
    __syncthreads();

    // =================================================================
    // Pass A: warp-per-cell. RGB load, gray->sg, histogram, HSV stats.
    // lane -> col = cx*16+(lane&15), rows cy*16 + (lane>>4) + 2k
    // =================================================================
    for (int cell = wid; cell < NCELL; cell += 32) {
        const int cy = cell / GRID, cx = cell % GRID;
        const int colg = cx * 16 + (lane & 15);
        const int row0 = cy * 16 + (lane >> 4);
        int* hc = hi + cell * 24;
        float acc[9];
        #pragma unroll
        for (int k = 0; k < 9; k++) acc[k] = 0.0f;

        #pragma unroll
        for (int k = 0; k < 8; k++) {
            const int rowg = row0 + 2 * k;
            const int p = rowg * WW + colg;
            const float r  = base[p];
            const float g  = base[NPIX + p];
            const float bl = base[2 * NPIX + p];
            const float gray = 0.299f * r + 0.587f * g + 0.114f * bl;
            sg[rowg * 132 + colg + 10] = gray;

            int ir = (int)floorf(r  * 8.0f); if ((unsigned)ir < 8u) atomicAdd(&hc[ir], 1);
            int ig = (int)floorf(g  * 8.0f); if ((unsigned)ig < 8u) atomicAdd(&hc[8 + ig], 1);
            int ib = (int)floorf(bl * 8.0f); if ((unsigned)ib < 8u) atomicAdd(&hc[16 + ib], 1);

            // HSV (matches reference branch order exactly)
            float maxc = fmaxf(r, fmaxf(g, bl));
            float minc = fminf(r, fminf(g, bl));
            float vv = maxc;
            float delta = maxc - minc;
            float ss = delta / (maxc + 1e-8f);
            float dsafe = (delta == 0.0f) ? 1.0f : delta;
            float rc = (maxc - r)  / dsafe;
            float gc = (maxc - g)  / dsafe;
            float bc = (maxc - bl) / dsafe;
            float hh;
            if (maxc == r)      hh = bc - gc;
            else if (maxc == g) hh = 2.0f + rc - bc;
            else                hh = 4.0f + gc - rc;
            hh = hh / 6.0f;
            hh = hh - floorf(hh);
            hh = hh * TWO_PI_F;

            acc[0] += r;  acc[1] += g;  acc[2] += bl;
            acc[3] += hh; acc[4] += ss; acc[5] += vv;
            acc[6] += hh * hh; acc[7] += ss * ss; acc[8] += vv * vv;
        }
        #pragma unroll
        for (int k = 0; k < 9; k++) {
            float x = acc[k];
            #pragma unroll
            for (int o = 16; o > 0; o >>= 1) x += __shfl_down_sync(0xffffffffu, x, o);
            if (lane == 0) ca[cell * 16 + k] = x;
        }
    }
    __syncthreads();   // sg complete

    // =================================================================
    // Pass B: warp-per-cell Sobel (clamp pad) + Laplacian (reflect pad)
    // reads sg only; no sync needed before gabor-h (also reads sg only)
    // =================================================================
    for (int cell = wid; cell < NCELL; cell += 32) {
        const int cy = cell / GRID, cx = cell % GRID;
        const int gx = cx * 16 + (lane & 15);
        const int row0 = cy * 16 + (lane >> 4);
        const int xm  = max(gx - 1, 0) + 10;
        const int xp  = min(gx + 1, WW - 1) + 10;
        const int x0  = gx + 10;
        const int Rxm = ((gx - 1) < 0      ? 1      : (gx - 1)) + 10;
        const int Rxp = ((gx + 1) > WW - 1 ? WW - 2 : (gx + 1)) + 10;
        float acc[6];
        #pragma unroll
        for (int k = 0; k < 6; k++) acc[k] = 0.0f;

        #pragma unroll
        for (int k = 0; k < 8; k++) {
            const int gy = row0 + 2 * k;
            const int y0 = gy;
            const int ym = max(gy - 1, 0);
            const int yp = min(gy + 1, HH - 1);
            float gxv = 0.125f * ((sg[ym*132+xp] + 2.0f*sg[y0*132+xp] + sg[yp*132+xp])
                                - (sg[ym*132+xm] + 2.0f*sg[y0*132+xm] + sg[yp*132+xm]));
            float gyv = 0.125f * ((sg[yp*132+xm] + 2.0f*sg[yp*132+x0] + sg[yp*132+xp])
                                - (sg[ym*132+xm] + 2.0f*sg[ym*132+x0] + sg[ym*132+xp]));
            float mag = sqrtf(gxv * gxv + gyv * gyv + 1e-8f);
            float d2  = gxv * gxv + gyv * gyv;
            float cav = (d2 > 0.0f) ? gxv * rsqrtf(d2) : 1.0f;

            const int Rym = ((gy - 1) < 0      ? 1      : (gy - 1));
            const int Ryp = ((gy + 1) > HH - 1 ? HH - 2 : (gy + 1));
            float nb = sg[Rym*132+Rxm] + sg[Rym*132+x0] + sg[Rym*132+Rxp]
                     + sg[y0*132+Rxm]                   + sg[y0*132+Rxp]
                     + sg[Ryp*132+Rxm] + sg[Ryp*132+x0] + sg[Ryp*132+Rxp];
            float lap = 0.0625f * nb - 0.5f * sg[y0*132+x0];

            acc[0] += mag; acc[1] += mag * mag; acc[2] += cav;
            acc[3] += lap; acc[4] += lap * lap; acc[5] += fabsf(lap);
        }
        #pragma unroll
        for (int k = 0; k < 6; k++) {
            float x = acc[k];
            #pragma unroll
            for (int o = 16; o > 0; o >>= 1) x += __shfl_down_sync(0xffffffffu, x, o);
            if (lane == 0) ca[cell * 16 + 9 + k] = x;
        }
    }

    // =================================================================
    // Gabor horizontal pass (rank-1 factor = center row), per orientation
    // 112 rows x 16 groups of 7 outputs; writes t0 / t1 (rows +10)
    // =================================================================
    for (int o = 0; o < 2; o++) {
        const float* gk = o ? gk1 : gk0;
        float* t = o ? t1 : t0;
        float f[21];
        #pragma unroll
        for (int d = 0; d < 21; d++) f[d] = __ldg(&gk[210 + d]);

        for (int g = tid; g < 112 * 16; g += 1024) {
            const int row = g >> 4, xg = g & 15;
            const float* bp = sg + row * 132 + xg * 7;
            float a[7];
            #pragma unroll
            for (int i = 0; i < 7; i++) a[i] = 0.0f;
            #pragma unroll
            for (int k = 0; k < 27; k++) {
                float v = bp[k];
                #pragma unroll
                for (int i = 0; i < 7; i++) {
                    int d = k - i;
                    if (d >= 0 && d < 21) a[i] = fmaf(f[d], v, a[i]);
                }
            }
            const int ob2 = (row + 10) * 112 + xg * 7;
            #pragma unroll
            for (int i = 0; i < 7; i++) t[ob2 + i] = a[i];
        }
    }
    __syncthreads();   // t0/t1 complete

    // =================================================================
    // Gabor vertical pass (factor = center col / center elem) + |.| +
    // per-cell sums via smem float atomics. 14 y-groups x 112 cols.
    // =================================================================
    for (int o = 0; o < 2; o++) {
        const float* gk = o ? gk1 : gk0;
        const float* t  = o ? t1 : t0;
        float inv = 1.0f / __ldg(&gk[220]);
        float g[21];
        #pragma unroll
        for (int d = 0; d < 21; d++) g[d] = __ldg(&gk[d * 21 + 10]) * inv;

        for (int idx = tid; idx < 14 * 112; idx += 1024) {
            const int x = idx % 112, yg = idx / 112, yb = yg * 8;
            float a[8];
            #pragma unroll
            for (int j = 0; j < 8; j++) a[j] = 0.0f;
            #pragma unroll
            for (int k = 0; k < 28; k++) {
                float v = t[(yb + k) * 112 + x];
                #pragma unroll
                for (int j = 0; j < 8; j++) {
                    int d = k - j;
                    if (d >= 0 && d < 21) a[j] = fmaf(g[d], v, a[j]);
                }
            }
            float s = 0.0f;
            #pragma unroll
            for (int j = 0; j < 8; j++) s += fabsf(a[j]);
            const int cellv = (yg >> 1) * GRID + (x >> 4);
            atomicAdd(&ga[cellv * 2 + o], s);
        }
    }
    __syncthreads();   // ca, ga, hi complete

    // =================================================================
    // Output phase
    // =================================================================
    float* ob = out + (size_t)b * NFEAT;
    const float inv256 = 1.0f / 256.0f;

    // histogram block (layout identical linearization: 3 + cell*24 + ch*8 + bin)
    for (int i = tid; i < 1176; i += 1024)
        ob[3 + i] = (float)hi[i] * inv256;
    // hsv grid means
    if (tid < 147) ob[1185 + tid] = ca[(tid / 3) * 16 + 3 + (tid % 3)] * inv256;
    // gabor cell means
    if (tid < 98) ob[1724 + (tid & 1) * NCELL + (tid >> 1)] = ga[(tid >> 1) * 2 + (tid & 1)] * inv256;
    // grad + tex per-cell stats
    if (tid >= 256 && tid < 256 + NCELL) {
        int cell = tid - 256;
        float smv = ca[cell*16+ 9], sq = ca[cell*16+10], cav = ca[cell*16+11];
        ob[1332 + cell*4 + 0] = smv * inv256;
        ob[1332 + cell*4 + 1] = sqrtf(fmaxf(0.0f, (sq - smv*smv*inv256) * (1.0f/255.0f)));
        ob[1332 + cell*4 + 2] = sq * inv256;
        ob[1332 + cell*4 + 3] = cav * inv256;
        float lm = ca[cell*16+12], lq = ca[cell*16+13], la = ca[cell*16+14];
        ob[1528 + cell*4 + 0] = lm * inv256;
        ob[1528 + cell*4 + 1] = sqrtf(fmaxf(0.0f, (lq - lm*lm*inv256) * (1.0f/255.0f)));
        ob[1528 + cell*4 + 2] = lq * inv256;
        ob[1528 + cell*4 + 3] = la * inv256;
    }
    // image-level sums
    if (tid >= 512 && tid < 521) {
        int k = tid - 512;
        float s = 0.0f;
        for (int c = 0; c < NCELL; c++) s += ca[c * 16 + k];
        is[k] = s;
    }
    __syncthreads();
    if (tid == 0) {
        const float N = (float)NPIX;
        ob[0] = is[0] / N;
        ob[1] = is[1] / N;
        ob[2] = is[2] / N;
        #pragma unroll
        for (int k = 0; k < 3; k++) {
            float smv = is[3 + k];
            float sqv = is[6 + k];
            float var = (sqv - smv * smv / N) / (N - 1.0f);
            ob[1179 + 2 * k] = smv / N;
            ob[1180 + 2 * k] = sqrtf(fmaxf(var, 0.0f));
        }
    }
}

// =====================================================================
extern "C" void kernel_launch(void* const* d_in, const int* in_sizes, int n_in,
                              void* d_out, int out_size)
{
    const float* img = (const float*)d_in[0];
    const float* gk0 = (const float*)d_in[1];
    const float* gk1 = (const float*)d_in[2];
    float* out = (float*)d_out;

    int B = in_sizes[0] / (3 * NPIX);

    cudaFuncSetAttribute(mega, cudaFuncAttributeMaxDynamicSharedMemorySize,
                         (int)MEGA_SMEM);
    mega<<<B, 1024, MEGA_SMEM>>>(img, gk0, gk1, out);
}

// round 9
// speedup vs baseline: 1.3122x; 1.3122x over previous
#include <cuda_runtime.h>
#include <math.h>

#define HH 112
#define WW 112
#define NPIX (HH*WW)          // 12544
#define GRID 7
#define NCELL 49
#define NFEAT 1822
#define BMAX 1024
#define TWO_PI_F 6.283185307179586f

// ---- scratch (static device arrays; no cudaMalloc anywhere) ----
__device__ float d_gray[(size_t)BMAX * NPIX];
__device__ float d_part[(size_t)BMAX * NCELL * 9];

// ---- f32x2 packed helpers (sm_100+) ----
__device__ __forceinline__ unsigned long long pk2(float a, float b) {
    unsigned long long r;
    asm("mov.b64 %0, {%1, %2};" : "=l"(r) : "f"(a), "f"(b));
    return r;
}
__device__ __forceinline__ unsigned long long fma2(unsigned long long a,
                                                   unsigned long long b,
                                                   unsigned long long c) {
    unsigned long long d;
    asm("fma.rn.f32x2 %0, %1, %2, %3;" : "=l"(d) : "l"(a), "l"(b), "l"(c));
    return d;
}
__device__ __forceinline__ void upk2(unsigned long long v, float& lo, float& hi) {
    asm("mov.b64 {%0, %1}, %2;" : "=f"(lo), "=f"(hi) : "l"(v));
}

// =====================================================================
// Kernel 1: per-cell features. 64 threads: q=tid&3 (4 cols via float4),
// r=tid>>2 (row 0..15). grid=(49,B).
// =====================================================================
__global__ void __launch_bounds__(64) cell_kernel(const float* __restrict__ img,
                                                  float* __restrict__ out)
{
    const int cell = blockIdx.x;
    const int b    = blockIdx.y;
    const int cy = cell / GRID, cx = cell % GRID;
    const int tid = threadIdx.x;
    const int q   = tid & 3;
    const int r   = tid >> 2;

    __shared__ float sg[18][18];
    __shared__ unsigned int shist[2][6];
    __shared__ float sred[15][2];
    __shared__ float stot[15];

    const float* base = img + (size_t)b * 3 * NPIX;
    const int oy = cy * 16 - 1;
    const int ox = cx * 16 - 1;
    const int gy  = cy * 16 + r;
    const int gx0 = cx * 16 + q * 4;
    const int p   = gy * WW + gx0;

    float4 r4 = *reinterpret_cast<const float4*>(base + p);
    float4 g4 = *reinterpret_cast<const float4*>(base + NPIX + p);
    float4 b4 = *reinterpret_cast<const float4*>(base + 2 * NPIX + p);
    float R[4]  = {r4.x, r4.y, r4.z, r4.w};
    float Gc[4] = {g4.x, g4.y, g4.z, g4.w};
    float Bl[4] = {b4.x, b4.y, b4.z, b4.w};
    float gr[4];
    #pragma unroll
    for (int j = 0; j < 4; j++) {
        gr[j] = 0.299f * R[j] + 0.587f * Gc[j] + 0.114f * Bl[j];
        sg[r + 1][q * 4 + 1 + j] = gr[j];
    }
    {   // gray out (float4 aligned)
        float4 go = make_float4(gr[0], gr[1], gr[2], gr[3]);
        *reinterpret_cast<float4*>(d_gray + (size_t)b * NPIX + p) = go;
    }

    // halo: 68 perimeter positions, coords clamped (clamp == edge pad)
    for (int i = tid; i < 68; i += 64) {
        int rr, cc;
        if (i < 18)      { rr = 0;          cc = i; }
        else if (i < 36) { rr = 17;         cc = i - 18; }
        else if (i < 52) { rr = i - 36 + 1; cc = 0; }
        else             { rr = i - 52 + 1; cc = 17; }
        int yy = min(max(oy + rr, 0), HH - 1);
        int xx = min(max(ox + cc, 0), WW - 1);
        int pp = yy * WW + xx;
        sg[rr][cc] = 0.299f * base[pp] + 0.587f * base[NPIX + pp] + 0.114f * base[2 * NPIX + pp];
    }
    __syncthreads();

    float acc[15];
    #pragma unroll
    for (int k = 0; k < 15; k++) acc[k] = 0.0f;

    // ---- Pass A: histogram (nibble-packed registers) + HSV ----
    unsigned int hR = 0, hG = 0, hB = 0;
    #pragma unroll
    for (int j = 0; j < 4; j++) {
        const float rr = R[j], gg = Gc[j], bb = Bl[j];
        int ir = (int)floorf(rr * 8.0f); if ((unsigned)ir < 8u) hR += 1u << (ir << 2);
        int ig = (int)floorf(gg * 8.0f); if ((unsigned)ig < 8u) hG += 1u << (ig << 2);
        int ib = (int)floorf(bb * 8.0f); if ((unsigned)ib < 8u) hB += 1u << (ib << 2);

        float maxc = fmaxf(rr, fmaxf(gg, bb));
        float minc = fminf(rr, fminf(gg, bb));
        float vv = maxc;
        float delta = maxc - minc;
        float dsafe = (delta == 0.0f) ? 1.0f : delta;
        float me = maxc + 1e-8f;
        float inv = __fdividef(1.0f, me * dsafe);      // one rcp for both divisors
        float ss = delta * dsafe * inv;
        float invd = me * inv;                          // = 1/dsafe
        float rc = (maxc - rr) * invd;
        float gc = (maxc - gg) * invd;
        float bc = (maxc - bb) * invd;
        float hh;
        if (maxc == rr)      hh = bc - gc;
        else if (maxc == gg) hh = 2.0f + rc - bc;
        else                 hh = 4.0f + gc - rc;
        hh = hh * (1.0f / 6.0f);
        hh = hh - floorf(hh);
        hh = hh * TWO_PI_F;

        acc[0] += rr; acc[1] += gg; acc[2] += bb;
        acc[3] += hh; acc[4] += ss; acc[5] += vv;
        acc[6] += hh * hh; acc[7] += ss * ss; acc[8] += vv * vv;
    }

    // ---- Pass B: Sobel (clamp via halo) + Laplacian (reflect) ----
    {
        float w0[6], w1[6], w2[6], colS[6], dd[6], lapTB[6];
        const bool eT = (gy == 0), eB = (gy == HH - 1);
        const bool eL = (gx0 == 0), eR = (gx0 == WW - 4);
        #pragma unroll
        for (int c = 0; c < 6; c++) {
            w0[c] = sg[r][q * 4 + c];
            w1[c] = sg[r + 1][q * 4 + c];
            w2[c] = sg[r + 2][q * 4 + c];
            colS[c] = w0[c] + 2.0f * w1[c] + w2[c];
            dd[c]   = w2[c] - w0[c];
            lapTB[c] = eT ? 2.0f * w2[c] : (eB ? 2.0f * w0[c] : (w0[c] + w2[c]));
        }
        #pragma unroll
        for (int j = 0; j < 4; j++) {
            float gxv = 0.125f * (colS[j + 2] - colS[j]);
            float gyv = 0.125f * (dd[j] + 2.0f * dd[j + 1] + dd[j + 2]);
            float d2  = gxv * gxv + gyv * gyv;
            float mag = sqrtf(d2 + 1e-8f);
            float ca  = (d2 > 0.0f) ? gxv * rsqrtf(d2) : 1.0f;

            float vL  = (eL && j == 0) ? lapTB[2] : lapTB[j];
            float w1L = (eL && j == 0) ? w1[2]    : w1[j];
            float vR  = (eR && j == 3) ? lapTB[3] : lapTB[j + 2];
            float w1R = (eR && j == 3) ? w1[3]    : w1[j + 2];
            float nb  = vL + lapTB[j + 1] + vR + w1L + w1R;
            float lap = nb * 0.0625f - 0.5f * w1[j + 1];

            acc[9]  += mag; acc[10] += mag * mag; acc[11] += ca;
            acc[12] += lap; acc[13] += lap * lap; acc[14] += fabsf(lap);
        }
    }

    // ---- reductions (2 warps) ----
    const unsigned int M4 = 0x0F0F0F0Fu;
    unsigned int h6[6] = { hR & M4, (hR >> 4) & M4,
                           hG & M4, (hG >> 4) & M4,
                           hB & M4, (hB >> 4) & M4 };
    const int lane = tid & 31, w = tid >> 5;
    #pragma unroll
    for (int k = 0; k < 6; k++) {
        unsigned int x = h6[k];
        #pragma unroll
        for (int o = 16; o > 0; o >>= 1) x += __shfl_down_sync(0xffffffffu, x, o);
        h6[k] = x;
    }
    #pragma unroll
    for (int k = 0; k < 15; k++) {
        float x = acc[k];
        #pragma unroll
        for (int o = 16; o > 0; o >>= 1) x += __shfl_down_sync(0xffffffffu, x, o);
        if (lane == 0) sred[k][w] = x;
    }
    if (lane == 0) {
        #pragma unroll
        for (int k = 0; k < 6; k++) shist[w][k] = h6[k];
    }
    __syncthreads();
    if (tid < 15) stot[tid] = sred[tid][0] + sred[tid][1];
    __syncthreads();

    float* ob = out + (size_t)b * NFEAT;
    if (tid < 24) {
        int c = tid >> 3, bin = tid & 7;
        int u = c * 2 + (bin & 1), sh = 8 * (bin >> 1);
        unsigned int cnt = ((shist[0][u] >> sh) & 0xFFu) + ((shist[1][u] >> sh) & 0xFFu);
        ob[3 + ((size_t)cell * 3 + c) * 8 + bin] = (float)cnt * (1.0f / 256.0f);
    }
    if (tid < 3) ob[1185 + cell * 3 + tid] = stot[3 + tid] * (1.0f / 256.0f);
    if (tid < 9) d_part[((size_t)b * NCELL + cell) * 9 + tid] = stot[tid];
    if (tid == 0) {
        float sm = stot[9], sq = stot[10];
        ob[1332 + cell * 4 + 0] = sm * (1.0f / 256.0f);
        ob[1332 + cell * 4 + 1] = sqrtf(fmaxf(0.0f, (sq - sm * sm * (1.0f / 256.0f)) * (1.0f / 255.0f)));
        ob[1332 + cell * 4 + 2] = sq * (1.0f / 256.0f);
        ob[1332 + cell * 4 + 3] = stot[11] * (1.0f / 256.0f);
        float lm = stot[12], lq = stot[13];
        ob[1528 + cell * 4 + 0] = lm * (1.0f / 256.0f);
        ob[1528 + cell * 4 + 1] = sqrtf(fmaxf(0.0f, (lq - lm * lm * (1.0f / 256.0f)) * (1.0f / 255.0f)));
        ob[1528 + cell * 4 + 2] = lq * (1.0f / 256.0f);
        ob[1528 + cell * 4 + 3] = stot[14] * (1.0f / 256.0f);
    }
}

// =====================================================================
// Kernel 2: fused separable Gabor (both orientations packed as f32x2),
// one block per image, + per-cell means + per-image finalize.
// smem: t (132x112 u64 pairs) | sg (112x136 f) | ga 98 f | is 16 f
// =====================================================================
#define T_U64    (132 * 112)
#define SG_OFF_F (T_U64 * 2)                 // float index of sg
#define GA_OFF_F (SG_OFF_F + 112 * 136)
#define IS_OFF_F (GA_OFF_F + 100)
#define GAB_SMEM ((size_t)(IS_OFF_F + 16) * sizeof(float))   // ~179.7 KB

__global__ void __launch_bounds__(768) gabor_fused(const float* __restrict__ gk0,
                                                   const float* __restrict__ gk1,
                                                   float* __restrict__ out)
{
    extern __shared__ float smf[];
    unsigned long long* t = reinterpret_cast<unsigned long long*>(smf);
    float* sg = smf + SG_OFF_F;
    float* ga = smf + GA_OFF_F;
    float* is = smf + IS_OFF_F;

    const int b   = blockIdx.x;
    const int tid = threadIdx.x;

    // zero halo rows of t (rows 0..9, 122..131)
    for (int i = tid; i < 20 * 112; i += 768) {
        int rr = i / 112, cc = i % 112;
        int row = (rr < 10) ? rr : rr + 112;
        t[row * 112 + cc] = 0ULL;
    }
    // zero halo cols of sg (cols 0..11, 124..135)
    for (int i = tid; i < 112 * 24; i += 768) {
        int rr = i / 24, cc = i % 24;
        int col = (cc < 12) ? cc : cc + 112;
        sg[rr * 136 + col] = 0.0f;
    }
    if (tid < 100) ga[tid] = 0.0f;

    // load gray image (float4), data at col+12
    const float* gr = d_gray + (size_t)b * NPIX;
    for (int i = tid; i < 112 * 28; i += 768) {
        int row = i / 28, j = i % 28;
        float4 v = *reinterpret_cast<const float4*>(gr + row * WW + j * 4);
        *reinterpret_cast<float4*>(sg + row * 136 + 12 + j * 4) = v;
    }

    // horizontal taps: (gk0 row10, gk1 row10) packed
    unsigned long long tapH[21];
    #pragma unroll
    for (int d = 0; d < 21; d++)
        tapH[d] = pk2(__ldg(&gk0[210 + d]), __ldg(&gk1[210 + d]));
    __syncthreads();

    // ---- horizontal pass: 112 rows x 16 groups of 7 outputs ----
    for (int g = tid; g < 112 * 16; g += 768) {
        const int row = g >> 4, xg = g & 15;
        const float* bp = sg + row * 136 + 2 + xg * 7;
        unsigned long long a[7];
        #pragma unroll
        for (int i = 0; i < 7; i++) a[i] = 0ULL;
        #pragma unroll
        for (int k = 0; k < 27; k++) {
            float v = bp[k];
            unsigned long long vp = pk2(v, v);
            #pragma unroll
            for (int i = 0; i < 7; i++) {
                int d = k - i;
                if (d >= 0 && d < 21) a[i] = fma2(tapH[d], vp, a[i]);
            }
        }
        const int ot = (row + 10) * 112 + xg * 7;
        #pragma unroll
        for (int i = 0; i < 7; i++) t[ot + i] = a[i];
    }

    // vertical taps: (col10/center) packed
    unsigned long long tapV[21];
    {
        float inv0 = __fdividef(1.0f, __ldg(&gk0[220]));
        float inv1 = __fdividef(1.0f, __ldg(&gk1[220]));
        #pragma unroll
        for (int d = 0; d < 21; d++)
            tapV[d] = pk2(__ldg(&gk0[d * 21 + 10]) * inv0,
                          __ldg(&gk1[d * 21 + 10]) * inv1);
    }
    __syncthreads();

    // ---- vertical pass: 14 y-groups of 8 outputs x 112 cols ----
    for (int g = tid; g < 14 * 112; g += 768) {
        const int x = g % 112, yg = g / 112, yb = yg * 8;
        unsigned long long a[8];
        #pragma unroll
        for (int j = 0; j < 8; j++) a[j] = 0ULL;
        #pragma unroll
        for (int k = 0; k < 28; k++) {
            unsigned long long vp = t[(yb + k) * 112 + x];
            #pragma unroll
            for (int j = 0; j < 8; j++) {
                int d = k - j;
                if (d >= 0 && d < 21) a[j] = fma2(tapV[d], vp, a[j]);
            }
        }
        float s0 = 0.0f, s1 = 0.0f;
        #pragma unroll
        for (int j = 0; j < 8; j++) {
            float lo, hi;
            upk2(a[j], lo, hi);
            s0 += fabsf(lo);
            s1 += fabsf(hi);
        }
        const int cellv = (yg >> 1) * GRID + (x >> 4);
        atomicAdd(&ga[cellv * 2 + 0], s0);
        atomicAdd(&ga[cellv * 2 + 1], s1);
    }

    // per-image sums from d_part (overlap with v-pass tail)
    if (tid >= 704 && tid < 713) {
        int k = tid - 704;
        const float* pp = d_part + (size_t)b * NCELL * 9;
        float s = 0.0f;
        for (int c = 0; c < NCELL; c++) s += pp[c * 9 + k];
        is[k] = s;
    }
    __syncthreads();

    float* ob = out + (size_t)b * NFEAT;
    if (tid < 98)
        ob[1724 + (tid & 1) * NCELL + (tid >> 1)] = ga[(tid >> 1) * 2 + (tid & 1)] * (1.0f / 256.0f);
    if (tid == 0) {
        const float N = (float)NPIX;
        ob[0] = is[0] / N;
        ob[1] = is[1] / N;
        ob[2] = is[2] / N;
        #pragma unroll
        for (int k = 0; k < 3; k++) {
            float smv = is[3 + k];
            float sqv = is[6 + k];
            float var = (sqv - smv * smv / N) / (N - 1.0f);
            ob[1179 + 2 * k] = smv / N;
            ob[1180 + 2 * k] = sqrtf(fmaxf(var, 0.0f));
        }
    }
}

// =====================================================================
extern "C" void kernel_launch(void* const* d_in, const int* in_sizes, int n_in,
                              void* d_out, int out_size)
{
    const float* img = (const float*)d_in[0];
    const float* gk0 = (const float*)d_in[1];
    const float* gk1 = (const float*)d_in[2];
    float* out = (float*)d_out;

    int B = in_sizes[0] / (3 * NPIX);
    if (B > BMAX) B = BMAX;

    cudaFuncSetAttribute(gabor_fused,
                         cudaFuncAttributeMaxDynamicSharedMemorySize,
                         (int)GAB_SMEM);

    cell_kernel<<<dim3(NCELL, B), 64>>>(img, out);
    gabor_fused<<<B, 768, GAB_SMEM>>>(gk0, gk1, out);
}